// round 14
// baseline (speedup 1.0000x reference)
#include <cuda_runtime.h>
#include <cuda_fp16.h>
#include <mma.h>
#include <cstdint>

using namespace nvcuda;

#define N_NODES   50000
#define PAD_NODES 50048        // multiple of 128 (GEMM M-tile)
#define N_EDGES   800000
#define D_IN      256
#define D_OUT     256

#define SCAN_BLKS 196          // 196*256 = 50176 >= N_NODES

// ---------------- static device scratch (no allocations) -------------------
__device__ __align__(16) __half g_xwh[(size_t)PAD_NODES * D_OUT];  // xw in fp16
__device__ __align__(16) int  g_cnt[2 * N_NODES];   // [0,N): deg  [N,2N): fill cursor
__device__ __align__(16) int  g_rowptr[N_NODES];    // block-local exclusive prefix
__device__ __align__(16) int  g_bsum[256];
__device__ __align__(16) int  g_boff[256];
__device__ __align__(16) unsigned int g_epk[N_EDGES];   // {val_fp16 : col_u16}

// ---------------------------------------------------------------------------
// Monolithic HMMA GEMM: xwh = (half)(x @ W), both inputs converted in-kernel.
// Block 128M x 128N, BK=32, 8 warps (4x2), warp tile 32x64, double-buffered.
// ---------------------------------------------------------------------------
#define BLK_M 128
#define BLK_N 128
#define BLK_K 32
#define A_LD  (BLK_K + 8)
#define B_LD  (BLK_N + 8)

__global__ __launch_bounds__(256)
void wmma_gemm_kernel(const float* __restrict__ x,
                      const float* __restrict__ W)
{
    __shared__ __half As[2][BLK_M * A_LD];
    __shared__ __half Bs[2][BLK_K * B_LD];
    __shared__ float  ebuf[8][16 * 16];

    const int t    = threadIdx.x;
    const int warp = t >> 5;
    const int lane = t & 31;
    const int wm   = warp & 3;
    const int wn   = warp >> 2;
    const int row0 = blockIdx.x * BLK_M;
    const int col0 = blockIdx.y * BLK_N;

    wmma::fragment<wmma::accumulator, 16, 16, 16, float> acc[2][4];
    #pragma unroll
    for (int i = 0; i < 2; i++)
        #pragma unroll
        for (int j = 0; j < 4; j++)
            wmma::fill_fragment(acc[i][j], 0.0f);

    // A: thread t covers row = t>>1, halves [(t&1)*16, +16) -- 4 float4 loads
    const int a_row = t >> 1;
    const int a_c16 = (t & 1) * 16;
    const int gm_a  = row0 + a_row;
    const bool a_ok = (gm_a < N_NODES);
    const float* a_ptr = x + (size_t)gm_a * D_IN + a_c16;

    auto load_a_g = [&](int k0, float4* r) {
        #pragma unroll
        for (int q = 0; q < 4; q++)
            r[q] = a_ok ? *reinterpret_cast<const float4*>(a_ptr + k0 + q * 4)
                        : make_float4(0.f, 0.f, 0.f, 0.f);
    };
    // B: 32 rows x 128 fp32 = 1024 float4; 4 per thread; converted on store.
    auto load_b_g = [&](int k0, float4* r) {
        #pragma unroll
        for (int q = 0; q < 4; q++) {
            const int f   = t + q * 256;
            const int row = f >> 5;           // 0..31
            const int c4  = (f & 31) * 4;     // 0..124
            r[q] = *reinterpret_cast<const float4*>(
                &W[(size_t)(k0 + row) * D_OUT + col0 + c4]);
        }
    };
    auto store_a_s = [&](int buf, const float4* r) {
        union { __half h[16]; uint4 u[2]; } pk;
        #pragma unroll
        for (int q = 0; q < 4; q++) {
            const __half2 h01 = __floats2half2_rn(r[q].x, r[q].y);
            const __half2 h23 = __floats2half2_rn(r[q].z, r[q].w);
            pk.h[q * 4 + 0] = __low2half(h01);
            pk.h[q * 4 + 1] = __high2half(h01);
            pk.h[q * 4 + 2] = __low2half(h23);
            pk.h[q * 4 + 3] = __high2half(h23);
        }
        uint4* dst = reinterpret_cast<uint4*>(&As[buf][a_row * A_LD + a_c16]);
        dst[0] = pk.u[0];
        dst[1] = pk.u[1];
    };
    auto store_b_s = [&](int buf, const float4* r) {
        #pragma unroll
        for (int q = 0; q < 4; q++) {
            const int f   = t + q * 256;
            const int row = f >> 5;
            const int c4  = (f & 31) * 4;
            const __half2 h01 = __floats2half2_rn(r[q].x, r[q].y);
            const __half2 h23 = __floats2half2_rn(r[q].z, r[q].w);
            uint2 u;
            u.x = *reinterpret_cast<const unsigned int*>(&h01);
            u.y = *reinterpret_cast<const unsigned int*>(&h23);
            *reinterpret_cast<uint2*>(&Bs[buf][row * B_LD + c4]) = u;
        }
    };

    float4 ra[4], rb[4];
    load_a_g(0, ra);
    load_b_g(0, rb);
    store_a_s(0, ra);
    store_b_s(0, rb);
    __syncthreads();

    const int NSTEP = D_IN / BLK_K;
    int buf = 0;

    for (int s = 0; s < NSTEP; s++) {
        if (s + 1 < NSTEP) {
            load_a_g((s + 1) * BLK_K, ra);
            load_b_g((s + 1) * BLK_K, rb);
        }

        #pragma unroll
        for (int kk = 0; kk < 2; kk++) {
            wmma::fragment<wmma::matrix_a, 16, 16, 16, __half, wmma::row_major> a0, a1;
            wmma::load_matrix_sync(a0, &As[buf][(wm * 32 +  0) * A_LD + kk * 16], A_LD);
            wmma::load_matrix_sync(a1, &As[buf][(wm * 32 + 16) * A_LD + kk * 16], A_LD);
            #pragma unroll
            for (int j = 0; j < 4; j++) {
                wmma::fragment<wmma::matrix_b, 16, 16, 16, __half, wmma::row_major> b;
                wmma::load_matrix_sync(b, &Bs[buf][(kk * 16) * B_LD + wn * 64 + j * 16], B_LD);
                wmma::mma_sync(acc[0][j], a0, b, acc[0][j]);
                wmma::mma_sync(acc[1][j], a1, b, acc[1][j]);
            }
        }

        if (s + 1 < NSTEP) {
            const int nb = buf ^ 1;
            store_a_s(nb, ra);
            store_b_s(nb, rb);
            __syncthreads();
            buf = nb;
        }
    }

    const int r  = lane >> 1;
    const int cc = (lane & 1) * 8;
    const int c0 = col0 + wn * 64;

    #pragma unroll
    for (int i = 0; i < 2; i++) {
        #pragma unroll
        for (int j = 0; j < 4; j++) {
            wmma::store_matrix_sync(ebuf[warp], acc[i][j], 16, wmma::mem_row_major);
            __syncwarp();
            const int grow = row0 + wm * 32 + i * 16 + r;
            if (grow < N_NODES) {
                union { __half h[8]; uint4 u; } pk;
                #pragma unroll
                for (int q = 0; q < 8; q++)
                    pk.h[q] = __float2half(ebuf[warp][r * 16 + cc + q]);
                *reinterpret_cast<uint4*>(&g_xwh[(size_t)grow * D_OUT + c0 + j * 16 + cc]) = pk.u;
            }
            __syncwarp();
        }
    }
}

// ---------------------------------------------------------------------------
// CSR construction — warp-shuffle scans, phase3 folded into consumers.
// ---------------------------------------------------------------------------
__global__ __launch_bounds__(256)
void count_kernel(const int* __restrict__ edge_row)
{
    const int e8 = (blockIdx.x * blockDim.x + threadIdx.x) * 8;
    if (e8 >= N_EDGES) return;
    // N_EDGES % 8 == 0 — no remainder path
    const int4 r0 = *reinterpret_cast<const int4*>(&edge_row[e8]);
    const int4 r1 = *reinterpret_cast<const int4*>(&edge_row[e8 + 4]);
    atomicAdd(&g_cnt[r0.x], 1);
    atomicAdd(&g_cnt[r0.y], 1);
    atomicAdd(&g_cnt[r0.z], 1);
    atomicAdd(&g_cnt[r0.w], 1);
    atomicAdd(&g_cnt[r1.x], 1);
    atomicAdd(&g_cnt[r1.y], 1);
    atomicAdd(&g_cnt[r1.z], 1);
    atomicAdd(&g_cnt[r1.w], 1);
}

// Phase 1: per-block (256) warp-shuffle scan; rowptr = block-local exclusive.
__global__ __launch_bounds__(256)
void scan_phase1()
{
    __shared__ int wsum[8];
    const int t    = threadIdx.x;
    const int lane = t & 31;
    const int wid  = t >> 5;
    const int i    = blockIdx.x * 256 + t;
    const int v    = (i < N_NODES) ? g_cnt[i] : 0;

    int inc = v;
    #pragma unroll
    for (int off = 1; off < 32; off <<= 1) {
        const int u = __shfl_up_sync(0xffffffffu, inc, off);
        if (lane >= off) inc += u;
    }
    if (lane == 31) wsum[wid] = inc;
    __syncthreads();
    if (wid == 0) {
        int ws = (lane < 8) ? wsum[lane] : 0;
        #pragma unroll
        for (int off = 1; off < 8; off <<= 1) {
            const int u = __shfl_up_sync(0xffffffffu, ws, off);
            if (lane >= off) ws += u;
        }
        if (lane < 8) wsum[lane] = ws;   // inclusive warp sums
    }
    __syncthreads();

    const int woff = (wid == 0) ? 0 : wsum[wid - 1];
    if (i < N_NODES) g_rowptr[i] = inc - v + woff;
    if (t == 255) g_bsum[blockIdx.x] = wsum[7];
}

// Phase 2: one block scans the block sums -> exclusive offsets.
__global__ __launch_bounds__(256)
void scan_phase2()
{
    __shared__ int wsum[8];
    const int t    = threadIdx.x;
    const int lane = t & 31;
    const int wid  = t >> 5;
    const int v    = (t < SCAN_BLKS) ? g_bsum[t] : 0;

    int inc = v;
    #pragma unroll
    for (int off = 1; off < 32; off <<= 1) {
        const int u = __shfl_up_sync(0xffffffffu, inc, off);
        if (lane >= off) inc += u;
    }
    if (lane == 31) wsum[wid] = inc;
    __syncthreads();
    if (wid == 0) {
        int ws = (lane < 8) ? wsum[lane] : 0;
        #pragma unroll
        for (int off = 1; off < 8; off <<= 1) {
            const int u = __shfl_up_sync(0xffffffffu, ws, off);
            if (lane >= off) ws += u;
        }
        if (lane < 8) wsum[lane] = ws;
    }
    __syncthreads();

    const int woff = (wid == 0) ? 0 : wsum[wid - 1];
    g_boff[t] = inc - v + woff;          // global exclusive block offset
}

__device__ __forceinline__ unsigned int pack_edge(int col, float v)
{
    const unsigned short hv = __half_as_ushort(__float2half_rn(v));
    return (unsigned int)col | ((unsigned int)hv << 16);
}

__device__ __forceinline__ int row_start(int r)
{
    return g_rowptr[r] + g_boff[r >> 8];
}

__global__ __launch_bounds__(256)
void fill_kernel(const int*   __restrict__ edge_row,
                 const int*   __restrict__ edge_col,
                 const float* __restrict__ edge_vals)
{
    const int e8 = (blockIdx.x * blockDim.x + threadIdx.x) * 8;
    if (e8 >= N_EDGES) return;
    const int4   r0 = *reinterpret_cast<const int4*>(&edge_row[e8]);
    const int4   r1 = *reinterpret_cast<const int4*>(&edge_row[e8 + 4]);
    const int4   c0 = *reinterpret_cast<const int4*>(&edge_col[e8]);
    const int4   c1 = *reinterpret_cast<const int4*>(&edge_col[e8 + 4]);
    const float4 v0 = *reinterpret_cast<const float4*>(&edge_vals[e8]);
    const float4 v1 = *reinterpret_cast<const float4*>(&edge_vals[e8 + 4]);

    int p;
    p = row_start(r0.x) + atomicAdd(&g_cnt[N_NODES + r0.x], 1);
    g_epk[p] = pack_edge(c0.x, v0.x);
    p = row_start(r0.y) + atomicAdd(&g_cnt[N_NODES + r0.y], 1);
    g_epk[p] = pack_edge(c0.y, v0.y);
    p = row_start(r0.z) + atomicAdd(&g_cnt[N_NODES + r0.z], 1);
    g_epk[p] = pack_edge(c0.z, v0.z);
    p = row_start(r0.w) + atomicAdd(&g_cnt[N_NODES + r0.w], 1);
    g_epk[p] = pack_edge(c0.w, v0.w);
    p = row_start(r1.x) + atomicAdd(&g_cnt[N_NODES + r1.x], 1);
    g_epk[p] = pack_edge(c1.x, v1.x);
    p = row_start(r1.y) + atomicAdd(&g_cnt[N_NODES + r1.y], 1);
    g_epk[p] = pack_edge(c1.y, v1.y);
    p = row_start(r1.z) + atomicAdd(&g_cnt[N_NODES + r1.z], 1);
    g_epk[p] = pack_edge(c1.z, v1.z);
    p = row_start(r1.w) + atomicAdd(&g_cnt[N_NODES + r1.w], 1);
    g_epk[p] = pack_edge(c1.w, v1.w);
}

// ---------------------------------------------------------------------------
// Monolithic SpMM: out = relu(A @ xwh + bias) — gather loop unchanged (R11).
// ---------------------------------------------------------------------------
__device__ __forceinline__ void fma_half8(float* acc, float v, uint4 m)
{
    const __half2* h = reinterpret_cast<const __half2*>(&m);
    #pragma unroll
    for (int q = 0; q < 4; q++) {
        const float2 f = __half22float2(h[q]);
        acc[q * 2 + 0] = fmaf(v, f.x, acc[q * 2 + 0]);
        acc[q * 2 + 1] = fmaf(v, f.y, acc[q * 2 + 1]);
    }
}

__device__ __forceinline__ float epk_val(unsigned int pk)
{
    return __half2float(__ushort_as_half((unsigned short)(pk >> 16)));
}

__global__ __launch_bounds__(256)
void spmm_kernel(const float* __restrict__ bias,
                 float*       __restrict__ out)
{
    const int row  = (blockIdx.x * blockDim.x + threadIdx.x) >> 5;
    const int lane = threadIdx.x & 31;
    if (row >= N_NODES) return;

    const int s = g_rowptr[row] + g_boff[row >> 8];
    const int e = (row + 1 < N_NODES)
                    ? (g_rowptr[row + 1] + g_boff[(row + 1) >> 8])
                    : N_EDGES;
    const int c = lane * 8;

    float acc[8];
    #pragma unroll
    for (int q = 0; q < 8; q++) acc[q] = 0.f;

    int base = s;
    while (base < e) {
        const int navail = min(32, e - base);

        unsigned int pk_lane = 0;
        if (lane < navail) pk_lane = __ldg(&g_epk[base + lane]);

        int j = 0;
        for (; j + 7 < navail; j += 8) {
            unsigned int pk[8];
            uint4 m[8];
            #pragma unroll
            for (int q = 0; q < 8; q++)
                pk[q] = __shfl_sync(0xffffffffu, pk_lane, j + q);
            #pragma unroll
            for (int q = 0; q < 8; q++)
                m[q] = __ldg(reinterpret_cast<const uint4*>(
                    &g_xwh[(size_t)(pk[q] & 0xFFFFu) * D_OUT + c]));
            #pragma unroll
            for (int q = 0; q < 8; q++)
                fma_half8(acc, epk_val(pk[q]), m[q]);
        }
        if (j + 3 < navail) {
            unsigned int pk[4];
            uint4 m[4];
            #pragma unroll
            for (int q = 0; q < 4; q++)
                pk[q] = __shfl_sync(0xffffffffu, pk_lane, j + q);
            #pragma unroll
            for (int q = 0; q < 4; q++)
                m[q] = __ldg(reinterpret_cast<const uint4*>(
                    &g_xwh[(size_t)(pk[q] & 0xFFFFu) * D_OUT + c]));
            #pragma unroll
            for (int q = 0; q < 4; q++)
                fma_half8(acc, epk_val(pk[q]), m[q]);
            j += 4;
        }
        for (; j < navail; j++) {
            const unsigned int pk = __shfl_sync(0xffffffffu, pk_lane, j);
            const uint4 m = __ldg(reinterpret_cast<const uint4*>(
                &g_xwh[(size_t)(pk & 0xFFFFu) * D_OUT + c]));
            fma_half8(acc, epk_val(pk), m);
        }
        base += navail;
    }

    const float4 b0 = *reinterpret_cast<const float4*>(&bias[c]);
    const float4 b1 = *reinterpret_cast<const float4*>(&bias[c + 4]);
    float4 o0, o1;
    o0.x = fmaxf(acc[0] + b0.x, 0.f);
    o0.y = fmaxf(acc[1] + b0.y, 0.f);
    o0.z = fmaxf(acc[2] + b0.z, 0.f);
    o0.w = fmaxf(acc[3] + b0.w, 0.f);
    o1.x = fmaxf(acc[4] + b1.x, 0.f);
    o1.y = fmaxf(acc[5] + b1.y, 0.f);
    o1.z = fmaxf(acc[6] + b1.z, 0.f);
    o1.w = fmaxf(acc[7] + b1.w, 0.f);

    float* dst = &out[(size_t)row * D_OUT + c];
    __stcs(reinterpret_cast<float4*>(dst),     o0);
    __stcs(reinterpret_cast<float4*>(dst + 4), o1);
}

// ---------------------------------------------------------------------------
// Launch:
//   side : monolithic GEMM (W + x converted in-kernel) -> ev_g
//   main : memset cnt ; count ; scan1 ; scan2 ; fill ; wait ev_g ; SpMM
// ---------------------------------------------------------------------------
static cudaStream_t g_side = nullptr;
static cudaEvent_t  g_fork = nullptr;
static cudaEvent_t  g_evg  = nullptr;
static void* g_cnt_ptr = nullptr;

extern "C" void kernel_launch(void* const* d_in, const int* in_sizes, int n_in,
                              void* d_out, int out_size)
{
    const float* x         = (const float*)d_in[0];
    const int*   edge_row  = (const int*)  d_in[1];
    const int*   edge_col  = (const int*)  d_in[2];
    const float* edge_vals = (const float*)d_in[3];
    const float* weight    = (const float*)d_in[4];
    const float* bias      = (const float*)d_in[5];
    float* out = (float*)d_out;

    if (g_side == nullptr) {
        cudaStreamCreateWithFlags(&g_side, cudaStreamNonBlocking);
        cudaEventCreateWithFlags(&g_fork, cudaEventDisableTiming);
        cudaEventCreateWithFlags(&g_evg,  cudaEventDisableTiming);
        cudaGetSymbolAddress(&g_cnt_ptr, g_cnt);
    }

    // Fork side stream
    cudaEventRecord(g_fork, 0);
    cudaStreamWaitEvent(g_side, g_fork, 0);

    // Side: monolithic GEMM (x and W converted in-kernel)
    {
        dim3 ggrid(PAD_NODES / BLK_M, D_OUT / BLK_N);
        wmma_gemm_kernel<<<ggrid, 256, 0, g_side>>>(x, weight);
        cudaEventRecord(g_evg, g_side);
    }

    // Main: CSR build (overlaps GEMM)
    cudaMemsetAsync(g_cnt_ptr, 0, 2 * N_NODES * sizeof(int), 0);
    count_kernel<<<(N_EDGES / 8 + 255) / 256, 256>>>(edge_row);
    scan_phase1<<<SCAN_BLKS, 256>>>();
    scan_phase2<<<1, 256>>>();
    fill_kernel<<<(N_EDGES / 8 + 255) / 256, 256>>>(edge_row, edge_col, edge_vals);

    // Main: SpMM after GEMM
    cudaStreamWaitEvent(0, g_evg, 0);
    const int spmm_blocks = (N_NODES * 32 + 255) / 256;
    spmm_kernel<<<spmm_blocks, 256>>>(bias, out);
}

// round 15
// speedup vs baseline: 1.1645x; 1.1645x over previous
#include <cuda_runtime.h>
#include <cuda_fp16.h>
#include <mma.h>
#include <cstdint>

using namespace nvcuda;

#define N_NODES   50000
#define PAD_NODES 50048        // multiple of 128 (GEMM M-tile)
#define N_EDGES   800000
#define D_IN      256
#define D_OUT     256

#define SCAN_BLKS 196          // 196*256 = 50176 >= N_NODES

// ---------------- static device scratch (no allocations) -------------------
__device__ __align__(16) __half g_wh [(size_t)D_IN * D_OUT];       // W in fp16
__device__ __align__(16) __half g_xwh[(size_t)PAD_NODES * D_OUT];  // xw in fp16
__device__ __align__(16) int  g_deg[N_NODES];
__device__ __align__(16) int  g_fill[N_NODES];
__device__ __align__(16) int  g_rowptr[N_NODES + 1];
__device__ __align__(16) int  g_bsum[256];
__device__ __align__(16) int  g_boff[256];
__device__ __align__(16) unsigned int g_epk[N_EDGES];   // {val_fp16 : col_u16}

// ---------------------------------------------------------------------------
// W fp32 -> fp16 (separate kernel; 2 us, fully overlapped — R13 fusion of this
// into the GEMM B-path regressed the GEMM and is reverted)
// ---------------------------------------------------------------------------
__global__ __launch_bounds__(256)
void convert_w_kernel(const float* __restrict__ W)
{
    const size_t idx = (size_t)blockIdx.x * blockDim.x + threadIdx.x;
    const size_t i4  = idx * 4;
    if (i4 >= (size_t)D_IN * D_OUT) return;
    const float4 v = *reinterpret_cast<const float4*>(&W[i4]);
    const __half2 h01 = __floats2half2_rn(v.x, v.y);
    const __half2 h23 = __floats2half2_rn(v.z, v.w);
    uint2 u;
    u.x = *reinterpret_cast<const unsigned int*>(&h01);
    u.y = *reinterpret_cast<const unsigned int*>(&h23);
    *reinterpret_cast<uint2*>(&g_wh[i4]) = u;
}

// ---------------------------------------------------------------------------
// Monolithic HMMA GEMM: xwh = (half)(x @ W) — R12 version (x converted
// in-kernel, B tiles fp16 from g_wh).
// ---------------------------------------------------------------------------
#define BLK_M 128
#define BLK_N 128
#define BLK_K 32
#define A_LD  (BLK_K + 8)
#define B_LD  (BLK_N + 8)

__global__ __launch_bounds__(256)
void wmma_gemm_kernel(const float* __restrict__ x)
{
    __shared__ __half As[2][BLK_M * A_LD];
    __shared__ __half Bs[2][BLK_K * B_LD];
    __shared__ float  ebuf[8][16 * 16];

    const int t    = threadIdx.x;
    const int warp = t >> 5;
    const int lane = t & 31;
    const int wm   = warp & 3;
    const int wn   = warp >> 2;
    const int row0 = blockIdx.x * BLK_M;
    const int col0 = blockIdx.y * BLK_N;

    wmma::fragment<wmma::accumulator, 16, 16, 16, float> acc[2][4];
    #pragma unroll
    for (int i = 0; i < 2; i++)
        #pragma unroll
        for (int j = 0; j < 4; j++)
            wmma::fill_fragment(acc[i][j], 0.0f);

    const int a_row = t >> 1;
    const int a_c16 = (t & 1) * 16;
    const int gm_a  = row0 + a_row;
    const bool a_ok = (gm_a < N_NODES);
    const float* a_ptr = x + (size_t)gm_a * D_IN + a_c16;

    auto load_a_g = [&](int k0, float4* r) {
        #pragma unroll
        for (int q = 0; q < 4; q++)
            r[q] = a_ok ? *reinterpret_cast<const float4*>(a_ptr + k0 + q * 4)
                        : make_float4(0.f, 0.f, 0.f, 0.f);
    };
    auto load_b_g = [&](int k0, uint4* r) {
        #pragma unroll
        for (int q = 0; q < 2; q++) {
            const int idx = t + q * 256;
            const int row = idx >> 4;
            const int c8  = (idx & 15) * 8;
            r[q] = *reinterpret_cast<const uint4*>(
                &g_wh[(size_t)(k0 + row) * D_OUT + col0 + c8]);
        }
    };
    auto store_a_s = [&](int buf, const float4* r) {
        union { __half h[16]; uint4 u[2]; } pk;
        #pragma unroll
        for (int q = 0; q < 4; q++) {
            const __half2 h01 = __floats2half2_rn(r[q].x, r[q].y);
            const __half2 h23 = __floats2half2_rn(r[q].z, r[q].w);
            pk.h[q * 4 + 0] = __low2half(h01);
            pk.h[q * 4 + 1] = __high2half(h01);
            pk.h[q * 4 + 2] = __low2half(h23);
            pk.h[q * 4 + 3] = __high2half(h23);
        }
        uint4* dst = reinterpret_cast<uint4*>(&As[buf][a_row * A_LD + a_c16]);
        dst[0] = pk.u[0];
        dst[1] = pk.u[1];
    };
    auto store_b_s = [&](int buf, const uint4* r) {
        #pragma unroll
        for (int q = 0; q < 2; q++) {
            const int idx = t + q * 256;
            const int row = idx >> 4;
            const int c8  = (idx & 15) * 8;
            *reinterpret_cast<uint4*>(&Bs[buf][row * B_LD + c8]) = r[q];
        }
    };

    float4 ra[4];
    uint4  rb[2];
    load_a_g(0, ra);
    load_b_g(0, rb);
    store_a_s(0, ra);
    store_b_s(0, rb);
    __syncthreads();

    const int NSTEP = D_IN / BLK_K;
    int buf = 0;

    for (int s = 0; s < NSTEP; s++) {
        if (s + 1 < NSTEP) {
            load_a_g((s + 1) * BLK_K, ra);
            load_b_g((s + 1) * BLK_K, rb);
        }

        #pragma unroll
        for (int kk = 0; kk < 2; kk++) {
            wmma::fragment<wmma::matrix_a, 16, 16, 16, __half, wmma::row_major> a0, a1;
            wmma::load_matrix_sync(a0, &As[buf][(wm * 32 +  0) * A_LD + kk * 16], A_LD);
            wmma::load_matrix_sync(a1, &As[buf][(wm * 32 + 16) * A_LD + kk * 16], A_LD);
            #pragma unroll
            for (int j = 0; j < 4; j++) {
                wmma::fragment<wmma::matrix_b, 16, 16, 16, __half, wmma::row_major> b;
                wmma::load_matrix_sync(b, &Bs[buf][(kk * 16) * B_LD + wn * 64 + j * 16], B_LD);
                wmma::mma_sync(acc[0][j], a0, b, acc[0][j]);
                wmma::mma_sync(acc[1][j], a1, b, acc[1][j]);
            }
        }

        if (s + 1 < NSTEP) {
            const int nb = buf ^ 1;
            store_a_s(nb, ra);
            store_b_s(nb, rb);
            __syncthreads();
            buf = nb;
        }
    }

    const int r  = lane >> 1;
    const int cc = (lane & 1) * 8;
    const int c0 = col0 + wn * 64;

    #pragma unroll
    for (int i = 0; i < 2; i++) {
        #pragma unroll
        for (int j = 0; j < 4; j++) {
            wmma::store_matrix_sync(ebuf[warp], acc[i][j], 16, wmma::mem_row_major);
            __syncwarp();
            const int grow = row0 + wm * 32 + i * 16 + r;
            if (grow < N_NODES) {
                union { __half h[8]; uint4 u; } pk;
                #pragma unroll
                for (int q = 0; q < 8; q++)
                    pk.h[q] = __float2half(ebuf[warp][r * 16 + cc + q]);
                *reinterpret_cast<uint4*>(&g_xwh[(size_t)grow * D_OUT + c0 + j * 16 + cc]) = pk.u;
            }
            __syncwarp();
        }
    }
}

// ---------------------------------------------------------------------------
// CSR construction — R12 count/fill (x4), warp-shuffle scans, 3 phases.
// ---------------------------------------------------------------------------
__global__ __launch_bounds__(256)
void count_kernel(const int* __restrict__ edge_row)
{
    const int e4 = (blockIdx.x * blockDim.x + threadIdx.x) * 4;
    if (e4 + 3 < N_EDGES) {
        const int4 r = *reinterpret_cast<const int4*>(&edge_row[e4]);
        atomicAdd(&g_deg[r.x], 1);
        atomicAdd(&g_deg[r.y], 1);
        atomicAdd(&g_deg[r.z], 1);
        atomicAdd(&g_deg[r.w], 1);
    } else {
        for (int e = e4; e < N_EDGES; e++)
            atomicAdd(&g_deg[edge_row[e]], 1);
    }
}

// Phase 1: per-block (256) warp-shuffle scan; writes local-exclusive + block sum.
__global__ __launch_bounds__(256)
void scan_phase1()
{
    __shared__ int wsum[8];
    const int t    = threadIdx.x;
    const int lane = t & 31;
    const int wid  = t >> 5;
    const int i    = blockIdx.x * 256 + t;
    const int v    = (i < N_NODES) ? g_deg[i] : 0;

    int inc = v;
    #pragma unroll
    for (int off = 1; off < 32; off <<= 1) {
        const int u = __shfl_up_sync(0xffffffffu, inc, off);
        if (lane >= off) inc += u;
    }
    if (lane == 31) wsum[wid] = inc;
    __syncthreads();
    if (wid == 0) {
        int ws = (lane < 8) ? wsum[lane] : 0;
        #pragma unroll
        for (int off = 1; off < 8; off <<= 1) {
            const int u = __shfl_up_sync(0xffffffffu, ws, off);
            if (lane >= off) ws += u;
        }
        if (lane < 8) wsum[lane] = ws;   // inclusive warp sums
    }
    __syncthreads();

    const int woff = (wid == 0) ? 0 : wsum[wid - 1];
    if (i < N_NODES) g_rowptr[i] = inc - v + woff;   // block-local exclusive
    if (t == 255) g_bsum[blockIdx.x] = wsum[7];      // block total
}

// Phase 2: one block scans the block sums -> exclusive offsets.
__global__ __launch_bounds__(256)
void scan_phase2()
{
    __shared__ int wsum[8];
    const int t    = threadIdx.x;
    const int lane = t & 31;
    const int wid  = t >> 5;
    const int v    = (t < SCAN_BLKS) ? g_bsum[t] : 0;

    int inc = v;
    #pragma unroll
    for (int off = 1; off < 32; off <<= 1) {
        const int u = __shfl_up_sync(0xffffffffu, inc, off);
        if (lane >= off) inc += u;
    }
    if (lane == 31) wsum[wid] = inc;
    __syncthreads();
    if (wid == 0) {
        int ws = (lane < 8) ? wsum[lane] : 0;
        #pragma unroll
        for (int off = 1; off < 8; off <<= 1) {
            const int u = __shfl_up_sync(0xffffffffu, ws, off);
            if (lane >= off) ws += u;
        }
        if (lane < 8) wsum[lane] = ws;
    }
    __syncthreads();

    const int woff = (wid == 0) ? 0 : wsum[wid - 1];
    g_boff[t] = inc - v + woff;
}

// Phase 3: materialize global rowptr (keeps SpMM/fill hot loops clean).
__global__ __launch_bounds__(256)
void scan_phase3()
{
    const int i = blockIdx.x * 256 + threadIdx.x;
    if (i < N_NODES) g_rowptr[i] += g_boff[blockIdx.x];
    if (i == 0) g_rowptr[N_NODES] = N_EDGES;
}

__device__ __forceinline__ unsigned int pack_edge(int col, float v)
{
    const unsigned short hv = __half_as_ushort(__float2half_rn(v));
    return (unsigned int)col | ((unsigned int)hv << 16);
}

__global__ __launch_bounds__(256)
void fill_kernel(const int*   __restrict__ edge_row,
                 const int*   __restrict__ edge_col,
                 const float* __restrict__ edge_vals)
{
    const int e4 = (blockIdx.x * blockDim.x + threadIdx.x) * 4;
    if (e4 + 3 < N_EDGES) {
        const int4   r = *reinterpret_cast<const int4*>(&edge_row[e4]);
        const int4   c = *reinterpret_cast<const int4*>(&edge_col[e4]);
        const float4 v = *reinterpret_cast<const float4*>(&edge_vals[e4]);
        int p;
        p = g_rowptr[r.x] + atomicAdd(&g_fill[r.x], 1);
        g_epk[p] = pack_edge(c.x, v.x);
        p = g_rowptr[r.y] + atomicAdd(&g_fill[r.y], 1);
        g_epk[p] = pack_edge(c.y, v.y);
        p = g_rowptr[r.z] + atomicAdd(&g_fill[r.z], 1);
        g_epk[p] = pack_edge(c.z, v.z);
        p = g_rowptr[r.w] + atomicAdd(&g_fill[r.w], 1);
        g_epk[p] = pack_edge(c.w, v.w);
    } else {
        for (int e = e4; e < N_EDGES; e++) {
            const int rr = edge_row[e];
            const int p = g_rowptr[rr] + atomicAdd(&g_fill[rr], 1);
            g_epk[p] = pack_edge(edge_col[e], edge_vals[e]);
        }
    }
}

// ---------------------------------------------------------------------------
// Monolithic SpMM: out = relu(A @ xwh + bias) — unchanged (R11/R12).
// ---------------------------------------------------------------------------
__device__ __forceinline__ void fma_half8(float* acc, float v, uint4 m)
{
    const __half2* h = reinterpret_cast<const __half2*>(&m);
    #pragma unroll
    for (int q = 0; q < 4; q++) {
        const float2 f = __half22float2(h[q]);
        acc[q * 2 + 0] = fmaf(v, f.x, acc[q * 2 + 0]);
        acc[q * 2 + 1] = fmaf(v, f.y, acc[q * 2 + 1]);
    }
}

__device__ __forceinline__ float epk_val(unsigned int pk)
{
    return __half2float(__ushort_as_half((unsigned short)(pk >> 16)));
}

__global__ __launch_bounds__(256)
void spmm_kernel(const float* __restrict__ bias,
                 float*       __restrict__ out)
{
    const int row  = (blockIdx.x * blockDim.x + threadIdx.x) >> 5;
    const int lane = threadIdx.x & 31;
    if (row >= N_NODES) return;

    const int s = g_rowptr[row];
    const int e = g_rowptr[row + 1];
    const int c = lane * 8;

    float acc[8];
    #pragma unroll
    for (int q = 0; q < 8; q++) acc[q] = 0.f;

    int base = s;
    while (base < e) {
        const int navail = min(32, e - base);

        unsigned int pk_lane = 0;
        if (lane < navail) pk_lane = __ldg(&g_epk[base + lane]);

        int j = 0;
        for (; j + 7 < navail; j += 8) {
            unsigned int pk[8];
            uint4 m[8];
            #pragma unroll
            for (int q = 0; q < 8; q++)
                pk[q] = __shfl_sync(0xffffffffu, pk_lane, j + q);
            #pragma unroll
            for (int q = 0; q < 8; q++)
                m[q] = __ldg(reinterpret_cast<const uint4*>(
                    &g_xwh[(size_t)(pk[q] & 0xFFFFu) * D_OUT + c]));
            #pragma unroll
            for (int q = 0; q < 8; q++)
                fma_half8(acc, epk_val(pk[q]), m[q]);
        }
        if (j + 3 < navail) {
            unsigned int pk[4];
            uint4 m[4];
            #pragma unroll
            for (int q = 0; q < 4; q++)
                pk[q] = __shfl_sync(0xffffffffu, pk_lane, j + q);
            #pragma unroll
            for (int q = 0; q < 4; q++)
                m[q] = __ldg(reinterpret_cast<const uint4*>(
                    &g_xwh[(size_t)(pk[q] & 0xFFFFu) * D_OUT + c]));
            #pragma unroll
            for (int q = 0; q < 4; q++)
                fma_half8(acc, epk_val(pk[q]), m[q]);
            j += 4;
        }
        for (; j < navail; j++) {
            const unsigned int pk = __shfl_sync(0xffffffffu, pk_lane, j);
            const uint4 m = __ldg(reinterpret_cast<const uint4*>(
                &g_xwh[(size_t)(pk & 0xFFFFu) * D_OUT + c]));
            fma_half8(acc, epk_val(pk), m);
        }
        base += navail;
    }

    const float4 b0 = *reinterpret_cast<const float4*>(&bias[c]);
    const float4 b1 = *reinterpret_cast<const float4*>(&bias[c + 4]);
    float4 o0, o1;
    o0.x = fmaxf(acc[0] + b0.x, 0.f);
    o0.y = fmaxf(acc[1] + b0.y, 0.f);
    o0.z = fmaxf(acc[2] + b0.z, 0.f);
    o0.w = fmaxf(acc[3] + b0.w, 0.f);
    o1.x = fmaxf(acc[4] + b1.x, 0.f);
    o1.y = fmaxf(acc[5] + b1.y, 0.f);
    o1.z = fmaxf(acc[6] + b1.z, 0.f);
    o1.w = fmaxf(acc[7] + b1.w, 0.f);

    float* dst = &out[(size_t)row * D_OUT + c];
    __stcs(reinterpret_cast<float4*>(dst),     o0);
    __stcs(reinterpret_cast<float4*>(dst + 4), o1);
}

// ---------------------------------------------------------------------------
// Launch:
//   side : cvt W -> monolithic GEMM (ev_g)
//   main : memset deg/fill ; count ; scan x3 ; fill ; wait ev_g ; SpMM
// ---------------------------------------------------------------------------
static cudaStream_t g_side = nullptr;
static cudaEvent_t  g_fork = nullptr;
static cudaEvent_t  g_evg  = nullptr;
static void* g_deg_ptr  = nullptr;
static void* g_fill_ptr = nullptr;

extern "C" void kernel_launch(void* const* d_in, const int* in_sizes, int n_in,
                              void* d_out, int out_size)
{
    const float* x         = (const float*)d_in[0];
    const int*   edge_row  = (const int*)  d_in[1];
    const int*   edge_col  = (const int*)  d_in[2];
    const float* edge_vals = (const float*)d_in[3];
    const float* weight    = (const float*)d_in[4];
    const float* bias      = (const float*)d_in[5];
    float* out = (float*)d_out;

    if (g_side == nullptr) {
        cudaStreamCreateWithFlags(&g_side, cudaStreamNonBlocking);
        cudaEventCreateWithFlags(&g_fork, cudaEventDisableTiming);
        cudaEventCreateWithFlags(&g_evg,  cudaEventDisableTiming);
        cudaGetSymbolAddress(&g_deg_ptr,  g_deg);
        cudaGetSymbolAddress(&g_fill_ptr, g_fill);
    }

    // Fork side stream
    cudaEventRecord(g_fork, 0);
    cudaStreamWaitEvent(g_side, g_fork, 0);

    // Side: W conversion + monolithic GEMM (x converted in-kernel)
    {
        const size_t nw4 = (size_t)D_IN * D_OUT / 4;
        convert_w_kernel<<<(int)((nw4 + 255) / 256), 256, 0, g_side>>>(weight);
        dim3 ggrid(PAD_NODES / BLK_M, D_OUT / BLK_N);
        wmma_gemm_kernel<<<ggrid, 256, 0, g_side>>>(x);
        cudaEventRecord(g_evg, g_side);
    }

    // Main: CSR build (overlaps GEMM)
    cudaMemsetAsync(g_deg_ptr,  0, N_NODES * sizeof(int), 0);
    cudaMemsetAsync(g_fill_ptr, 0, N_NODES * sizeof(int), 0);
    count_kernel<<<(N_EDGES / 4 + 255) / 256, 256>>>(edge_row);
    scan_phase1<<<SCAN_BLKS, 256>>>();
    scan_phase2<<<1, 256>>>();
    scan_phase3<<<SCAN_BLKS, 256>>>();
    fill_kernel<<<(N_EDGES / 4 + 255) / 256, 256>>>(edge_row, edge_col, edge_vals);

    // Main: SpMM after GEMM
    cudaStreamWaitEvent(0, g_evg, 0);
    const int spmm_blocks = (N_NODES * 32 + 255) / 256;
    spmm_kernel<<<spmm_blocks, 256>>>(bias, out);
}